// round 13
// baseline (speedup 1.0000x reference)
#include <cuda_runtime.h>
#include <cuda_fp16.h>
#include <math.h>
#include <stdint.h>

// Problem dims
#define BB   64
#define PP   196
#define ENCD 2048
#define HD   1024
#define AD   1024
#define ED   512
#define VD   10000
#define TCD  32
#define TD   31
#define XD   (ED+ENCD)
#define G4H  (4*HD)
#define MB   (TD*BB)      // 1984
#define KSPL 4
#define KCH  (ENCD/KSPL)  // 512

// Output layout offsets (float32 elements)
#define O_PRED  0L
#define N_PRED  ((long)BB*TD*VD)
#define O_ALPHA (N_PRED)
#define N_ALPHA ((long)BB*TD*PP)
#define O_CAPS  (O_ALPHA + N_ALPHA)
#define O_DLEN  (O_CAPS + (long)BB*TCD)
#define O_IND   (O_DLEN + BB)

// -------- scratch --------
__device__ int    g_ind[BB];
__device__ int    g_declens[BB];
__device__ int    g_caps[BB*TCD];
__device__ int    g_nvalid;
__device__ int    g_tcnt[TD];
__device__ int    g_toff[TD];
__device__ int    g_vsrc[MB];
__device__ int    g_vdst[MB];
__device__ float  g_c[BB*HD];
__device__ float  g_decpart[2*BB*AD];
__device__ float  g_betapart[2*BB*ENCD];
__device__ float  g_score[BB*PP];
__device__ float  g_gpart[6*BB*G4H];          // 0..3 awe K-split, 4..5 hh K-split
__device__ float  g_P[(long)MB*G4H];
__device__ float  g_bias_ihh[G4H];
// fp16 activations
__device__ __half g_mean_h[BB*ENCD];
__device__ __half g_hhf[BB*HD];
__device__ __half g_awehf[BB*ENCD];
__device__ __half g_hallhf[(long)MB*HD];
__device__ __half g_embt_h[(long)MB*ED];
__device__ __half g_encatt_hf[(long)BB*PP*AD];   // 25.7 MB
__device__ __half g_eohf[(long)BB*PP*ENCD];      // 51.4 MB (sorted)
// fp16 weights
__device__ __half g_Wenc_h [AD*ENCD];
__device__ __half g_Wdec_h [AD*HD];
__device__ __half g_Wbeta_h[ENCD*HD];
__device__ __half g_Whh_h  [G4H*HD];
__device__ __half g_Wih_h  [(long)G4H*XD];
__device__ __half g_Wfc_h  [(long)VD*HD];
__device__ __half g_Winh_h [HD*ENCD];
__device__ __half g_Winc_h [HD*ENCD];

__device__ __forceinline__ void mma_f16(float* c, const uint32_t* a, const uint32_t* b) {
    asm volatile("mma.sync.aligned.m16n8k16.row.col.f32.f16.f16.f32 "
                 "{%0,%1,%2,%3}, {%4,%5,%6,%7}, {%8,%9}, {%0,%1,%2,%3};"
                 : "+f"(c[0]), "+f"(c[1]), "+f"(c[2]), "+f"(c[3])
                 : "r"(a[0]), "r"(a[1]), "r"(a[2]), "r"(a[3]),
                   "r"(b[0]), "r"(b[1]));
}

__device__ __forceinline__ void cp16(uint32_t daddr, const void* src, int sz) {
    asm volatile("cp.async.cg.shared.global [%0], [%1], 16, %2;"
                 :: "r"(daddr), "l"(src), "r"(sz));
}

// ---------------------------------------------------------------
// small kernels
// ---------------------------------------------------------------
__global__ void sort_kernel(const int* __restrict__ lengths,
                            const int* __restrict__ caps_in,
                            float* __restrict__ out)
{
    int b = threadIdx.x;
    if (b < BB) {
        int len = lengths[b];
        int rank = 0;
        for (int b2 = 0; b2 < BB; b2++) {
            int l2 = lengths[b2];
            rank += (l2 > len) || (l2 == len && b2 < b);
        }
        g_ind[rank] = b;
    }
    __syncthreads();
    if (b < BB) {
        int i = g_ind[b];
        int dl = lengths[i] - 1;
        g_declens[b] = dl;
        out[O_DLEN + b] = (float)dl;
        out[O_IND  + b] = (float)i;
        for (int j = 0; j < TCD; j++) {
            int cv = caps_in[i*TCD + j];
            g_caps[b*TCD + j] = cv;
            out[O_CAPS + b*TCD + j] = (float)cv;
        }
    }
    __syncthreads();
    if (b < TD) {
        int cnt = 0;
        for (int b2 = 0; b2 < BB; b2++) cnt += (g_declens[b2] > b);
        g_tcnt[b] = cnt;
    }
    __syncthreads();
    if (b == 0) {
        int off = 0;
        for (int t = 0; t < TD; t++) { g_toff[t] = off; off += g_tcnt[t]; }
        g_nvalid = off;
    }
    __syncthreads();
    if (b < TD) {
        int off = g_toff[b], cnt = g_tcnt[b];
        for (int i = 0; i < cnt; i++) {
            g_vsrc[off + i] = b*BB + i;       // t = b(thread idx), batch = i
            g_vdst[off + i] = i*TD + b;
        }
    }
}

// zero-fill masked pred rows + masked alpha rows
__global__ __launch_bounds__(256)
void zero_masked_kernel(float* __restrict__ out)
{
    int row = blockIdx.x;                 // row = b*TD + t
    int b = row / TD, t = row % TD;
    if (t < g_declens[b]) return;
    int tid = threadIdx.x;
    float4 z = make_float4(0.f, 0.f, 0.f, 0.f);
    float4* dp = reinterpret_cast<float4*>(out + (long)row*VD);
    for (int i = tid; i < VD/4; i += 256) dp[i] = z;
    float* da = out + O_ALPHA + (long)row*PP;
    for (int i = tid; i < PP; i += 256) da[i] = 0.f;
}

__global__ void bias_combine_kernel(const float* __restrict__ b_ih,
                                    const float* __restrict__ b_hh)
{
    int n = blockIdx.x*blockDim.x + threadIdx.x;
    if (n < G4H) g_bias_ihh[n] = b_ih[n] + b_hh[n];
}

// all weight conversions in one kernel
struct CvtSegs {
    const float4* src[8];
    __half2*      dst[8];
    long          cum[9];
};
__global__ void cvt_all_kernel(CvtSegs segs)
{
    long i = (long)blockIdx.x*blockDim.x + threadIdx.x;
    if (i >= segs.cum[8]) return;
    int s = 0;
    #pragma unroll
    for (int k = 1; k < 8; k++) s += (i >= segs.cum[k]);
    long j = i - segs.cum[s];
    float4 v = segs.src[s][j];
    segs.dst[s][j*2]   = __floats2half2_rn(v.x, v.y);
    segs.dst[s][j*2+1] = __floats2half2_rn(v.z, v.w);
}

__global__ void embt_kernel(const float* __restrict__ emb)
{
    long idx = (long)blockIdx.x*blockDim.x + threadIdx.x;
    if (idx >= (long)MB*ED) return;
    int row = (int)(idx / ED), j = (int)(idx % ED);
    int t = row / BB, b = row % BB;
    int cap = g_caps[b*TCD + t];
    g_embt_h[idx] = __float2half(emb[(long)cap*ED + j]);
}

// one pass: gather-sorted eo -> fp16 staged copy AND column mean
__global__ void mean_eohf_kernel(const float* __restrict__ enc_out)
{
    int e = blockIdx.x*blockDim.x + threadIdx.x;
    int b = blockIdx.y;
    if (e >= ENCD) return;
    long src = ((long)g_ind[b]*PP)*ENCD + e;
    long dst = ((long)b*PP)*ENCD + e;
    float acc = 0.f;
    for (int p = 0; p < PP; p++) {
        float v = enc_out[src + (long)p*ENCD];
        g_eohf[dst + (long)p*ENCD] = __float2half(v);
        acc += v;
    }
    g_mean_h[b*ENCD + e] = __float2half(acc / (float)PP);
}

// ---------------------------------------------------------------
// FP16 64x64 GEMM, cp.async 2-stage (4 warps):  EPI 0 fp32+bias, 5 fp16+bias
// (used only for h0/c0 prologue)
// ---------------------------------------------------------------
template<int EPI>
__global__ __launch_bounds__(128)
void fgemm64_kernel(const __half* __restrict__ A, int lda,
                    const __half* __restrict__ W, int ldw,
                    const float* __restrict__ bias,
                    void* __restrict__ Cv, int ldc,
                    int M, int N, int K)
{
    constexpr int BM=64, BN=64, BK=32, LD=BK+8, NT=128;
    __shared__ __half As[2][BM*LD];
    __shared__ __half Bs[2][BN*LD];

    const int tid = threadIdx.x;
    const int m0 = blockIdx.y*BM, n0 = blockIdx.x*BN;
    const int warp = tid >> 5, lane = tid & 31;
    const int wm = (warp % 2)*32, wn = (warp / 2)*32;
    const int g = lane >> 2, tg = lane & 3;

    const uint32_t sAbase = (uint32_t)__cvta_generic_to_shared(&As[0][0]);
    const uint32_t sBbase = (uint32_t)__cvta_generic_to_shared(&Bs[0][0]);

    float acc[2][4][4];
    #pragma unroll
    for (int i=0;i<2;i++)
        #pragma unroll
        for (int j=0;j<4;j++)
            #pragma unroll
            for (int q=0;q<4;q++) acc[i][j][q]=0.f;

    const int KT = K / BK;

    auto load_stage = [&](int st, int k0) {
        uint32_t ab = sAbase + (uint32_t)st*(BM*LD*2);
        #pragma unroll
        for (int s = tid; s < BM*(BK/8); s += NT) {
            int r = s >> 2, kk = (s & 3)*8;
            int row = m0 + r;
            const __half* srcp = A + (long)(row < M ? row : 0)*lda + k0 + kk;
            cp16(ab + (uint32_t)(r*LD + kk)*2, srcp, row < M ? 16 : 0);
        }
        uint32_t bb = sBbase + (uint32_t)st*(BN*LD*2);
        #pragma unroll
        for (int s = tid; s < BN*(BK/8); s += NT) {
            int r = s >> 2, kk = (s & 3)*8;
            int n = n0 + r;
            const __half* srcp = W + (long)(n < N ? n : 0)*ldw + k0 + kk;
            cp16(bb + (uint32_t)(r*LD + kk)*2, srcp, n < N ? 16 : 0);
        }
        asm volatile("cp.async.commit_group;" ::: "memory");
    };

    load_stage(0, 0);
    for (int kt = 0; kt < KT; kt++) {
        if (kt + 1 < KT) {
            load_stage((kt + 1) & 1, (kt + 1)*BK);
            asm volatile("cp.async.wait_group 1;" ::: "memory");
        } else {
            asm volatile("cp.async.wait_group 0;" ::: "memory");
        }
        __syncthreads();
        const __half* Ast = As[kt & 1];
        const __half* Bst = Bs[kt & 1];
        #pragma unroll
        for (int kk = 0; kk < BK; kk += 16) {
            uint32_t af[2][4], bf[4][2];
            #pragma unroll
            for (int i=0;i<2;i++) {
                int r0 = (wm + i*16 + g)*LD + kk + 2*tg;
                int r1 = (wm + i*16 + g + 8)*LD + kk + 2*tg;
                af[i][0] = *reinterpret_cast<const uint32_t*>(&Ast[r0]);
                af[i][1] = *reinterpret_cast<const uint32_t*>(&Ast[r1]);
                af[i][2] = *reinterpret_cast<const uint32_t*>(&Ast[r0 + 8]);
                af[i][3] = *reinterpret_cast<const uint32_t*>(&Ast[r1 + 8]);
            }
            #pragma unroll
            for (int j=0;j<4;j++) {
                int rb = (wn + j*8 + g)*LD + kk + 2*tg;
                bf[j][0] = *reinterpret_cast<const uint32_t*>(&Bst[rb]);
                bf[j][1] = *reinterpret_cast<const uint32_t*>(&Bst[rb + 8]);
            }
            #pragma unroll
            for (int i=0;i<2;i++)
                #pragma unroll
                for (int j=0;j<4;j++)
                    mma_f16(acc[i][j], af[i], bf[j]);
        }
        __syncthreads();
    }

    float* Cf = (float*)Cv;
    __half* Ch = (__half*)Cv;
    #pragma unroll
    for (int i=0;i<2;i++) {
        #pragma unroll
        for (int ci=0;ci<2;ci++) {
            int m = m0 + wm + i*16 + g + ci*8;
            if (m >= M) continue;
            #pragma unroll
            for (int j=0;j<4;j++) {
                #pragma unroll
                for (int cj=0;cj<2;cj++) {
                    int n = n0 + wn + j*8 + 2*tg + cj;
                    if (n >= N) continue;
                    float v = acc[i][j][ci*2+cj];
                    if (EPI == 0) Cf[(long)m*ldc + n] = v + bias[n];
                    else          Ch[(long)m*ldc + n] = __float2half(v + bias[n]);
                }
            }
        }
    }
}

// ---------------------------------------------------------------
// FP16 128x128 GEMM, cp.async 2-stage (8 warps, 32x64/warp):
//  EPI 0 fp32+bias, 5 fp16+bias, 7 compacted preds (gather rows, scatter out)
// ---------------------------------------------------------------
template<int EPI>
__global__ __launch_bounds__(256)
void fgemm128_kernel(const __half* __restrict__ A, int lda,
                     const __half* __restrict__ W, int ldw,
                     const float* __restrict__ bias,
                     void* __restrict__ Cv, int ldc,
                     int M, int N, int K)
{
    constexpr int BM=128, BN=128, BK=32, LD=BK+8, NT=256;
    __shared__ __half As[2][BM*LD];
    __shared__ __half Bs[2][BN*LD];

    const int tid = threadIdx.x;
    const int m0 = blockIdx.y*BM, n0 = blockIdx.x*BN;
    int Meff = M;
    if (EPI == 7) {
        Meff = g_nvalid;
        if (m0 >= Meff) return;
    }
    const int warp = tid >> 5, lane = tid & 31;
    const int wm = (warp % 4)*32, wn = (warp / 4)*64;
    const int g = lane >> 2, tg = lane & 3;

    const uint32_t sAbase = (uint32_t)__cvta_generic_to_shared(&As[0][0]);
    const uint32_t sBbase = (uint32_t)__cvta_generic_to_shared(&Bs[0][0]);

    float acc[2][8][4];
    #pragma unroll
    for (int i=0;i<2;i++)
        #pragma unroll
        for (int j=0;j<8;j++)
            #pragma unroll
            for (int q=0;q<4;q++) acc[i][j][q]=0.f;

    const int KT = K / BK;

    auto load_stage = [&](int st, int k0) {
        uint32_t ab = sAbase + (uint32_t)st*(BM*LD*2);
        #pragma unroll
        for (int s = tid; s < BM*(BK/8); s += NT) {
            int r = s >> 2, kk = (s & 3)*8;
            int row = m0 + r;
            long srow = 0;
            if (row < Meff) srow = (EPI == 7) ? (long)g_vsrc[row] : (long)row;
            const __half* srcp = A + srow*lda + k0 + kk;
            cp16(ab + (uint32_t)(r*LD + kk)*2, srcp, row < Meff ? 16 : 0);
        }
        uint32_t bb = sBbase + (uint32_t)st*(BN*LD*2);
        #pragma unroll
        for (int s = tid; s < BN*(BK/8); s += NT) {
            int r = s >> 2, kk = (s & 3)*8;
            int n = n0 + r;
            const __half* srcp = W + (long)(n < N ? n : 0)*ldw + k0 + kk;
            cp16(bb + (uint32_t)(r*LD + kk)*2, srcp, n < N ? 16 : 0);
        }
        asm volatile("cp.async.commit_group;" ::: "memory");
    };

    load_stage(0, 0);
    for (int kt = 0; kt < KT; kt++) {
        if (kt + 1 < KT) {
            load_stage((kt + 1) & 1, (kt + 1)*BK);
            asm volatile("cp.async.wait_group 1;" ::: "memory");
        } else {
            asm volatile("cp.async.wait_group 0;" ::: "memory");
        }
        __syncthreads();
        const __half* Ast = As[kt & 1];
        const __half* Bst = Bs[kt & 1];
        #pragma unroll
        for (int kk = 0; kk < BK; kk += 16) {
            uint32_t af[2][4], bf[8][2];
            #pragma unroll
            for (int i=0;i<2;i++) {
                int r0 = (wm + i*16 + g)*LD + kk + 2*tg;
                int r1 = (wm + i*16 + g + 8)*LD + kk + 2*tg;
                af[i][0] = *reinterpret_cast<const uint32_t*>(&Ast[r0]);
                af[i][1] = *reinterpret_cast<const uint32_t*>(&Ast[r1]);
                af[i][2] = *reinterpret_cast<const uint32_t*>(&Ast[r0 + 8]);
                af[i][3] = *reinterpret_cast<const uint32_t*>(&Ast[r1 + 8]);
            }
            #pragma unroll
            for (int j=0;j<8;j++) {
                int rb = (wn + j*8 + g)*LD + kk + 2*tg;
                bf[j][0] = *reinterpret_cast<const uint32_t*>(&Bst[rb]);
                bf[j][1] = *reinterpret_cast<const uint32_t*>(&Bst[rb + 8]);
            }
            #pragma unroll
            for (int i=0;i<2;i++)
                #pragma unroll
                for (int j=0;j<8;j++)
                    mma_f16(acc[i][j], af[i], bf[j]);
        }
        __syncthreads();
    }

    float* Cf = (float*)Cv;
    __half* Ch = (__half*)Cv;
    #pragma unroll
    for (int i=0;i<2;i++) {
        #pragma unroll
        for (int ci=0;ci<2;ci++) {
            int m = m0 + wm + i*16 + g + ci*8;
            if (m >= Meff) continue;
            long orow = (EPI == 7) ? (long)g_vdst[m] : (long)m;
            #pragma unroll
            for (int j=0;j<8;j++) {
                #pragma unroll
                for (int cj=0;cj<2;cj++) {
                    int n = n0 + wn + j*8 + 2*tg + cj;
                    if (n >= N) continue;
                    float v = acc[i][j][ci*2+cj] + bias[n];
                    if      (EPI == 0) Cf[orow*ldc + n] = v;
                    else if (EPI == 7) Cf[orow*ldc + n] = v;
                    else               Ch[orow*ldc + n] = __float2half(v);
                }
            }
        }
    }
}

// ---------------------------------------------------------------
// FP16 64x128 GEMM, cp.async 2-stage (4 warps, 32x64/warp):
//  MODE 0: hstep slice — A=g_hhf, W=[Wdec|Wbeta|Whh] concat; z in {0,1}, KC=512
//  MODE 1: awe partial — A=g_awehf, W=Wih[:,512:]; z in {0..3}, KC=512
// ---------------------------------------------------------------
template<int MODE>
__global__ __launch_bounds__(128)
void fgemmW_kernel()
{
    constexpr int BM=64, BN=128, BK=32, LD=BK+8, NT=128;
    constexpr int KC = 512;
    constexpr int KT = KC / BK;    // 16
    __shared__ __half As[2][BM*LD];
    __shared__ __half Bs[2][BN*LD];

    const int tid = threadIdx.x;
    const int n0 = blockIdx.x*BN;
    const int z = blockIdx.z;
    const long kbase = (long)z*KC;
    const int lda = (MODE == 0) ? HD : ENCD;
    const __half* Ap = (MODE == 0) ? g_hhf : g_awehf;
    const int warp = tid >> 5, lane = tid & 31;
    const int wm = (warp & 1)*32, wn = (warp >> 1)*64;
    const int g = lane >> 2, tg = lane & 3;

    const uint32_t sAbase = (uint32_t)__cvta_generic_to_shared(&As[0][0]);
    const uint32_t sBbase = (uint32_t)__cvta_generic_to_shared(&Bs[0][0]);

    float acc[2][8][4];
    #pragma unroll
    for (int i=0;i<2;i++)
        #pragma unroll
        for (int j=0;j<8;j++)
            #pragma unroll
            for (int q=0;q<4;q++) acc[i][j][q]=0.f;

    auto load_stage = [&](int st, int k0) {
        uint32_t ab = sAbase + (uint32_t)st*(BM*LD*2);
        #pragma unroll
        for (int s = tid; s < BM*(BK/8); s += NT) {
            int r = s >> 2, kk = (s & 3)*8;
            cp16(ab + (uint32_t)(r*LD + kk)*2,
                 Ap + (long)r*lda + kbase + k0 + kk, 16);
        }
        uint32_t bb = sBbase + (uint32_t)st*(BN*LD*2);
        #pragma unroll
        for (int s = tid; s < BN*(BK/8); s += NT) {
            int r = s >> 2, kk = (s & 3)*8;
            int gn = n0 + r;
            const __half* wrow;
            if (MODE == 0) {
                if (gn < 1024)      wrow = g_Wdec_h  + (long)gn*HD;
                else if (gn < 3072) wrow = g_Wbeta_h + (long)(gn-1024)*HD;
                else                wrow = g_Whh_h   + (long)(gn-3072)*HD;
            } else {
                wrow = g_Wih_h + (long)gn*XD + ED;
            }
            cp16(bb + (uint32_t)(r*LD + kk)*2, wrow + kbase + k0 + kk, 16);
        }
        asm volatile("cp.async.commit_group;" ::: "memory");
    };

    load_stage(0, 0);
    for (int kt = 0; kt < KT; kt++) {
        if (kt + 1 < KT) {
            load_stage((kt + 1) & 1, (kt + 1)*BK);
            asm volatile("cp.async.wait_group 1;" ::: "memory");
        } else {
            asm volatile("cp.async.wait_group 0;" ::: "memory");
        }
        __syncthreads();
        const __half* Ast = As[kt & 1];
        const __half* Bst = Bs[kt & 1];
        #pragma unroll
        for (int kk = 0; kk < BK; kk += 16) {
            uint32_t af[2][4], bf[8][2];
            #pragma unroll
            for (int i=0;i<2;i++) {
                int r0 = (wm + i*16 + g)*LD + kk + 2*tg;
                int r1 = (wm + i*16 + g + 8)*LD + kk + 2*tg;
                af[i][0] = *reinterpret_cast<const uint32_t*>(&Ast[r0]);
                af[i][1] = *reinterpret_cast<const uint32_t*>(&Ast[r1]);
                af[i][2] = *reinterpret_cast<const uint32_t*>(&Ast[r0 + 8]);
                af[i][3] = *reinterpret_cast<const uint32_t*>(&Ast[r1 + 8]);
            }
            #pragma unroll
            for (int j=0;j<8;j++) {
                int rb = (wn + j*8 + g)*LD + kk + 2*tg;
                bf[j][0] = *reinterpret_cast<const uint32_t*>(&Bst[rb]);
                bf[j][1] = *reinterpret_cast<const uint32_t*>(&Bst[rb + 8]);
            }
            #pragma unroll
            for (int i=0;i<2;i++)
                #pragma unroll
                for (int j=0;j<8;j++)
                    mma_f16(acc[i][j], af[i], bf[j]);
        }
        __syncthreads();
    }

    #pragma unroll
    for (int i=0;i<2;i++) {
        #pragma unroll
        for (int ci=0;ci<2;ci++) {
            int m = wm + i*16 + g + ci*8;
            #pragma unroll
            for (int j=0;j<8;j++) {
                #pragma unroll
                for (int cj=0;cj<2;cj++) {
                    int n = n0 + wn + j*8 + 2*tg + cj;
                    float v = acc[i][j][ci*2+cj];
                    if (MODE == 0) {
                        if (n < 1024)
                            g_decpart[(long)z*BB*AD + m*AD + n] = v;
                        else if (n < 3072)
                            g_betapart[(long)z*BB*ENCD + m*ENCD + (n-1024)] = v;
                        else
                            g_gpart[(long)(4+z)*BB*G4H + m*G4H + (n-3072)] = v;
                    } else {
                        g_gpart[(long)z*BB*G4H + m*G4H + n] = v;
                    }
                }
            }
        }
    }
}

// ---------------------------------------------------------------
// Attention scores (grid (BB,14), 128 threads; 14 p's per block)
// ---------------------------------------------------------------
__global__ __launch_bounds__(128)
void att_score_kernel(const float* __restrict__ wfull,
                      const float* __restrict__ bfull,
                      const float* __restrict__ bdec, int t)
{
    const int b = blockIdx.x;
    if (t >= g_declens[b]) return;

    __shared__ float s_dec[AD];
    __shared__ float s_wf[AD];

    const int pbase = blockIdx.y*14;
    const int tid = threadIdx.x;
    const int warp = tid >> 5, lane = tid & 31;

    for (int i = tid; i < AD; i += 128) {
        s_dec[i] = g_decpart[b*AD + i] + g_decpart[BB*AD + b*AD + i] + bdec[i];
        s_wf[i]  = wfull[i];
    }
    __syncthreads();

    const float bf = bfull[0];
    for (int pp = warp; pp < 14; pp += 4) {
        int p = pbase + pp;
        const __half2* row = reinterpret_cast<const __half2*>(
            g_encatt_hf + ((long)b*PP + p)*AD);
        float acc = 0.f;
        #pragma unroll 8
        for (int a2 = lane; a2 < AD/2; a2 += 32) {
            __half2 e2 = row[a2];
            int a = a2*2;
            float v0 = __half2float(__low2half(e2))  + s_dec[a];
            float v1 = __half2float(__high2half(e2)) + s_dec[a+1];
            v0 = v0 > 0.f ? v0 : 0.f;
            v1 = v1 > 0.f ? v1 : 0.f;
            acc = fmaf(v0, s_wf[a], acc);
            acc = fmaf(v1, s_wf[a+1], acc);
        }
        #pragma unroll
        for (int o = 16; o > 0; o >>= 1) acc += __shfl_down_sync(0xffffffffu, acc, o);
        if (lane == 0) g_score[b*PP + p] = acc + bf;
    }
}

// ---------------------------------------------------------------
// Fused softmax + context + awe. grid (ENCD/512, BB), 512 threads.
// ---------------------------------------------------------------
__global__ __launch_bounds__(512)
void ctx_awe_kernel(const float* __restrict__ bbeta,
                    float* __restrict__ out_alphas, int t)
{
    const int b = blockIdx.y;
    if (t >= g_declens[b]) return;

    __shared__ float s_al[PP];
    __shared__ float s_red[16];
    __shared__ float s_ctx[2*512];
    const int tid = threadIdx.x;
    const int warp = tid >> 5, lane = tid & 31;

    float v = (tid < PP) ? g_score[b*PP + tid] : -INFINITY;
    float m = v;
    #pragma unroll
    for (int o = 16; o > 0; o >>= 1) m = fmaxf(m, __shfl_xor_sync(0xffffffffu, m, o));
    if (lane == 0) s_red[warp] = m;
    __syncthreads();
    if (warp == 0) {
        float mm = (lane < 16) ? s_red[lane] : -INFINITY;
        #pragma unroll
        for (int o = 8; o > 0; o >>= 1) mm = fmaxf(mm, __shfl_xor_sync(0xffffffffu, mm, o));
        if (lane == 0) s_red[0] = mm;
    }
    __syncthreads();
    const float bmax = s_red[0];
    float e = (tid < PP) ? expf(v - bmax) : 0.f;
    float s = e;
    #pragma unroll
    for (int o = 16; o > 0; o >>= 1) s += __shfl_xor_sync(0xffffffffu, s, o);
    __syncthreads();
    if (lane == 0) s_red[warp] = s;
    __syncthreads();
    if (warp == 0) {
        float ss = (lane < 16) ? s_red[lane] : 0.f;
        #pragma unroll
        for (int o = 8; o > 0; o >>= 1) ss += __shfl_xor_sync(0xffffffffu, ss, o);
        if (lane == 0) s_red[0] = ss;
    }
    __syncthreads();
    const float inv = 1.f / s_red[0];
    if (tid < PP) {
        float al = e * inv;
        s_al[tid] = al;
        if (blockIdx.x == 0)
            out_alphas[((long)b*TD + t)*PP + tid] = al;
    }
    __syncthreads();

    const int half = tid >> 8;
    const int et = tid & 255;
    int e2 = blockIdx.x*256 + et;
    const int p0 = half*98;
    const __half2* base = reinterpret_cast<const __half2*>(g_eohf)
                        + ((long)b*PP + p0)*(ENCD/2) + e2;
    float a0 = 0.f, a1 = 0.f;
    #pragma unroll 7
    for (int p = 0; p < 98; p++) {
        __half2 vv = base[(long)p*(ENCD/2)];
        float al = s_al[p0 + p];
        a0 = fmaf(__half2float(__low2half(vv)),  al, a0);
        a1 = fmaf(__half2float(__high2half(vv)), al, a1);
    }
    s_ctx[tid*2]   = a0;
    s_ctx[tid*2+1] = a1;
    __syncthreads();

    if (tid < 256) {
        float c0 = s_ctx[tid*2]   + s_ctx[(tid+256)*2];
        float c1 = s_ctx[tid*2+1] + s_ctx[(tid+256)*2+1];
        int ee = e2*2;
        float bp0 = g_betapart[b*ENCD + ee]     + g_betapart[BB*ENCD + b*ENCD + ee]     + bbeta[ee];
        float bp1 = g_betapart[b*ENCD + ee + 1] + g_betapart[BB*ENCD + b*ENCD + ee + 1] + bbeta[ee+1];
        float w0 = (1.f/(1.f+expf(-bp0))) * c0;
        float w1 = (1.f/(1.f+expf(-bp1))) * c1;
        *reinterpret_cast<__half2*>(g_awehf + b*ENCD + ee) = __floats2half2_rn(w0, w1);
    }
}

// LSTM cell, 2 elems/thread: gates = P[t] + 6 partials; active b only
__global__ __launch_bounds__(256)
void lstm_kernel(int t)
{
    int idx = blockIdx.x*blockDim.x + threadIdx.x;
    if (idx >= BB*HD/2) return;
    int b = idx / (HD/2);
    if (t >= g_declens[b]) return;
    int j = (idx % (HD/2))*2;
    long base = (long)b*G4H;
    long pbase = ((long)t*BB + b)*G4H;
    float2 gi = *reinterpret_cast<const float2*>(&g_P[pbase + j]);
    float2 gf = *reinterpret_cast<const float2*>(&g_P[pbase + HD + j]);
    float2 gg = *reinterpret_cast<const float2*>(&g_P[pbase + 2*HD + j]);
    float2 go = *reinterpret_cast<const float2*>(&g_P[pbase + 3*HD + j]);
    #pragma unroll
    for (int s = 0; s < 6; s++) {
        long pb = (long)s*BB*G4H + base;
        float2 a  = *reinterpret_cast<const float2*>(&g_gpart[pb + j]);
        float2 bq = *reinterpret_cast<const float2*>(&g_gpart[pb + HD + j]);
        float2 c2 = *reinterpret_cast<const float2*>(&g_gpart[pb + 2*HD + j]);
        float2 d2 = *reinterpret_cast<const float2*>(&g_gpart[pb + 3*HD + j]);
        gi.x += a.x;  gi.y += a.y;
        gf.x += bq.x; gf.y += bq.y;
        gg.x += c2.x; gg.y += c2.y;
        go.x += d2.x; go.y += d2.y;
    }
    float2 cold = *reinterpret_cast<const float2*>(&g_c[b*HD + j]);
    float si0 = 1.f/(1.f+expf(-gi.x)), si1 = 1.f/(1.f+expf(-gi.y));
    float sf0 = 1.f/(1.f+expf(-gf.x)), sf1 = 1.f/(1.f+expf(-gf.y));
    float so0 = 1.f/(1.f+expf(-go.x)), so1 = 1.f/(1.f+expf(-go.y));
    float cn0 = sf0*cold.x + si0*tanhf(gg.x);
    float cn1 = sf1*cold.y + si1*tanhf(gg.y);
    float hn0 = so0*tanhf(cn0);
    float hn1 = so1*tanhf(cn1);
    *reinterpret_cast<__half2*>(&g_hallhf[((long)t*BB + b)*HD + j]) = __floats2half2_rn(hn0, hn1);
    *reinterpret_cast<__half2*>(&g_hhf[b*HD + j]) = __floats2half2_rn(hn0, hn1);
    *reinterpret_cast<float2*>(&g_c[b*HD + j]) = make_float2(cn0, cn1);
}

// ---------------------------------------------------------------
extern "C" void kernel_launch(void* const* d_in, const int* in_sizes, int n_in,
                              void* d_out, int out_size)
{
    const float* enc_out  = (const float*)d_in[0];
    const int*   caps_in  = (const int*)  d_in[1];
    const int*   lengths  = (const int*)  d_in[2];
    const float* W_enc    = (const float*)d_in[3];
    const float* b_enc    = (const float*)d_in[4];
    const float* W_dec    = (const float*)d_in[5];
    const float* b_dec    = (const float*)d_in[6];
    const float* W_full   = (const float*)d_in[7];
    const float* b_full   = (const float*)d_in[8];
    const float* emb      = (const float*)d_in[9];
    const float* W_ih     = (const float*)d_in[10];
    const float* b_ih     = (const float*)d_in[11];
    const float* W_hh     = (const float*)d_in[12];
    const float* b_hh     = (const float*)d_in[13];
    const float* W_init_h = (const float*)d_in[14];
    const float* b_init_h = (const float*)d_in[15];
    const float* W_init_c = (const float*)d_in[16];
    const float* b_init_c = (const float*)d_in[17];
    const float* W_beta   = (const float*)d_in[18];
    const float* b_beta   = (const float*)d_in[19];
    const float* W_fc     = (const float*)d_in[20];
    const float* b_fc     = (const float*)d_in[21];
    float* out = (float*)d_out;

    float *p_c,*p_P,*p_bihh;
    __half *p_meanh,*p_hhf,*p_hallhf,*p_embth,*p_enchf,*p_eohf;
    __half *p_Wenc,*p_Wdec,*p_Wbeta,*p_Whh,*p_Wih,*p_Wfc,*p_Winh,*p_Winc;
    cudaGetSymbolAddress((void**)&p_c,       g_c);
    cudaGetSymbolAddress((void**)&p_P,       g_P);
    cudaGetSymbolAddress((void**)&p_bihh,    g_bias_ihh);
    cudaGetSymbolAddress((void**)&p_meanh,   g_mean_h);
    cudaGetSymbolAddress((void**)&p_hhf,     g_hhf);
    cudaGetSymbolAddress((void**)&p_hallhf,  g_hallhf);
    cudaGetSymbolAddress((void**)&p_embth,   g_embt_h);
    cudaGetSymbolAddress((void**)&p_enchf,   g_encatt_hf);
    cudaGetSymbolAddress((void**)&p_eohf,    g_eohf);
    cudaGetSymbolAddress((void**)&p_Wenc,    g_Wenc_h);
    cudaGetSymbolAddress((void**)&p_Wdec,    g_Wdec_h);
    cudaGetSymbolAddress((void**)&p_Wbeta,   g_Wbeta_h);
    cudaGetSymbolAddress((void**)&p_Whh,     g_Whh_h);
    cudaGetSymbolAddress((void**)&p_Wih,     g_Wih_h);
    cudaGetSymbolAddress((void**)&p_Wfc,     g_Wfc_h);
    cudaGetSymbolAddress((void**)&p_Winh,    g_Winh_h);
    cudaGetSymbolAddress((void**)&p_Winc,    g_Winc_h);

    // ---------- prologue ----------
    sort_kernel<<<1, 64>>>(lengths, caps_in, out);
    zero_masked_kernel<<<BB*TD, 256>>>(out);
    bias_combine_kernel<<<G4H/256, 256>>>(b_ih, b_hh);

    {
        CvtSegs cs;
        const float* srcs[8] = {W_enc, W_dec, W_beta, W_hh, W_ih, W_fc, W_init_h, W_init_c};
        __half* dsts[8] = {p_Wenc, p_Wdec, p_Wbeta, p_Whh, p_Wih, p_Wfc, p_Winh, p_Winc};
        long lens[8] = {(long)AD*ENCD, (long)AD*HD, (long)ENCD*HD, (long)G4H*HD,
                        (long)G4H*XD, (long)VD*HD, (long)HD*ENCD, (long)HD*ENCD};
        long cum = 0;
        for (int s = 0; s < 8; s++) {
            cs.src[s] = (const float4*)srcs[s];
            cs.dst[s] = (__half2*)dsts[s];
            cs.cum[s] = cum;
            cum += lens[s]/4;
        }
        cs.cum[8] = cum;
        cvt_all_kernel<<<(int)((cum + 255)/256), 256>>>(cs);
    }

    embt_kernel<<<(int)(((long)MB*ED + 255)/256), 256>>>(emb);
    mean_eohf_kernel<<<dim3(ENCD/256, BB), 256>>>(enc_out);

    // h0 (fp16) / c0 (fp32) : (64 x 1024), K=2048
    {
        dim3 grid(HD/64, 1, 1);
        fgemm64_kernel<5><<<grid, 128>>>(p_meanh, ENCD, p_Winh, ENCD, b_init_h, p_hhf, HD, BB, HD, ENCD);
        fgemm64_kernel<0><<<grid, 128>>>(p_meanh, ENCD, p_Winc, ENCD, b_init_c, p_c,   HD, BB, HD, ENCD);
    }

    // enc_att : (12544 x 1024), K=2048 -> fp16
    {
        dim3 grid(AD/128, (BB*PP)/128);
        fgemm128_kernel<5><<<grid, 256>>>(p_eohf, ENCD, p_Wenc, ENCD, b_enc,
                                          p_enchf, AD, BB*PP, AD, ENCD);
    }

    // P = embt @ W_ih[:, :512]^T + (b_ih+b_hh) : (1984 x 4096), K=512
    {
        dim3 grid(G4H/128, (MB + 127)/128);
        fgemm128_kernel<0><<<grid, 256>>>(p_embth, ED, p_Wih, XD, p_bihh,
                                          p_P, G4H, MB, G4H, ED);
    }

    // ---------- recurrence (5 launches/step) ----------
    for (int t = 0; t < TD; t++) {
        {
            dim3 grid((1024+2048+4096)/128, 1, 2);     // 56 x 2 blocks
            fgemmW_kernel<0><<<grid, 128>>>();
        }
        att_score_kernel<<<dim3(BB, 14), 128>>>(W_full, b_full, b_dec, t);
        ctx_awe_kernel<<<dim3(ENCD/512, BB), 512>>>(b_beta, out + O_ALPHA, t);
        {
            dim3 grid(G4H/128, 1, KSPL);               // 32 x 4 blocks
            fgemmW_kernel<1><<<grid, 128>>>();
        }
        lstm_kernel<<<(BB*HD/2 + 255)/256, 256>>>(t);
    }

    // ---------- compacted predictions : (n_valid x 10000), K=1024 ----------
    {
        dim3 grid((VD + 127)/128, (MB + 127)/128);
        fgemm128_kernel<7><<<grid, 256>>>(p_hallhf, HD, p_Wfc, HD, b_fc,
                                          out + O_PRED, VD, MB, VD, HD);
    }
}

// round 14
// speedup vs baseline: 1.0590x; 1.0590x over previous
#include <cuda_runtime.h>
#include <cuda_fp16.h>
#include <math.h>
#include <stdint.h>

// Problem dims
#define BB   64
#define PP   196
#define ENCD 2048
#define HD   1024
#define AD   1024
#define ED   512
#define VD   10000
#define TCD  32
#define TD   31
#define XD   (ED+ENCD)
#define G4H  (4*HD)
#define MB   (TD*BB)      // 1984
#define KSPL 4
#define KCH  (ENCD/KSPL)  // 512

// Output layout offsets (float32 elements)
#define O_PRED  0L
#define N_PRED  ((long)BB*TD*VD)
#define O_ALPHA (N_PRED)
#define N_ALPHA ((long)BB*TD*PP)
#define O_CAPS  (O_ALPHA + N_ALPHA)
#define O_DLEN  (O_CAPS + (long)BB*TCD)
#define O_IND   (O_DLEN + BB)

// -------- scratch --------
__device__ int    g_ind[BB];
__device__ int    g_declens[BB];
__device__ int    g_caps[BB*TCD];
__device__ int    g_nvalid;
__device__ int    g_tcnt[TD];
__device__ int    g_toff[TD];
__device__ int    g_vsrc[MB];
__device__ int    g_vdst[MB];
__device__ float  g_c[BB*HD];
__device__ float  g_decpart[2*BB*AD];
__device__ float  g_betapart[2*BB*ENCD];
__device__ float  g_score[BB*PP];
__device__ float  g_gpart[6*BB*G4H];          // 0..3 awe K-split, 4..5 hh K-split
__device__ float  g_P[(long)MB*G4H];
__device__ float  g_bias_ihh[G4H];
// fp16 activations
__device__ __half g_mean_h[BB*ENCD];
__device__ __half g_hhf[BB*HD];
__device__ __half g_awehf[BB*ENCD];
__device__ __half g_hallhf[(long)MB*HD];
__device__ __half g_embt_h[(long)MB*ED];
__device__ __half g_encatt_hf[(long)BB*PP*AD];   // 25.7 MB
__device__ __half g_eohf[(long)BB*PP*ENCD];      // 51.4 MB (sorted)
// fp16 weights
__device__ __half g_Wenc_h [AD*ENCD];
__device__ __half g_Wdec_h [AD*HD];
__device__ __half g_Wbeta_h[ENCD*HD];
__device__ __half g_Whh_h  [G4H*HD];
__device__ __half g_Wih_h  [(long)G4H*XD];
__device__ __half g_Wfc_h  [(long)VD*HD];
__device__ __half g_Winh_h [HD*ENCD];
__device__ __half g_Winc_h [HD*ENCD];

__device__ __forceinline__ void mma_f16(float* c, const uint32_t* a, const uint32_t* b) {
    asm volatile("mma.sync.aligned.m16n8k16.row.col.f32.f16.f16.f32 "
                 "{%0,%1,%2,%3}, {%4,%5,%6,%7}, {%8,%9}, {%0,%1,%2,%3};"
                 : "+f"(c[0]), "+f"(c[1]), "+f"(c[2]), "+f"(c[3])
                 : "r"(a[0]), "r"(a[1]), "r"(a[2]), "r"(a[3]),
                   "r"(b[0]), "r"(b[1]));
}

__device__ __forceinline__ void cp16(uint32_t daddr, const void* src, int sz) {
    asm volatile("cp.async.cg.shared.global [%0], [%1], 16, %2;"
                 :: "r"(daddr), "l"(src), "r"(sz));
}

// ---------------------------------------------------------------
// small kernels
// ---------------------------------------------------------------
__global__ void sort_kernel(const int* __restrict__ lengths,
                            const int* __restrict__ caps_in,
                            float* __restrict__ out)
{
    int b = threadIdx.x;
    if (b < BB) {
        int len = lengths[b];
        int rank = 0;
        for (int b2 = 0; b2 < BB; b2++) {
            int l2 = lengths[b2];
            rank += (l2 > len) || (l2 == len && b2 < b);
        }
        g_ind[rank] = b;
    }
    __syncthreads();
    if (b < BB) {
        int i = g_ind[b];
        int dl = lengths[i] - 1;
        g_declens[b] = dl;
        out[O_DLEN + b] = (float)dl;
        out[O_IND  + b] = (float)i;
        for (int j = 0; j < TCD; j++) {
            int cv = caps_in[i*TCD + j];
            g_caps[b*TCD + j] = cv;
            out[O_CAPS + b*TCD + j] = (float)cv;
        }
    }
    __syncthreads();
    if (b < TD) {
        int cnt = 0;
        for (int b2 = 0; b2 < BB; b2++) cnt += (g_declens[b2] > b);
        g_tcnt[b] = cnt;
    }
    __syncthreads();
    if (b == 0) {
        int off = 0;
        for (int t = 0; t < TD; t++) { g_toff[t] = off; off += g_tcnt[t]; }
        g_nvalid = off;
    }
    __syncthreads();
    if (b < TD) {
        int off = g_toff[b], cnt = g_tcnt[b];
        for (int i = 0; i < cnt; i++) {
            g_vsrc[off + i] = b*BB + i;       // t = b(thread idx), batch = i
            g_vdst[off + i] = i*TD + b;
        }
    }
}

// zero-fill masked pred rows + masked alpha rows
__global__ __launch_bounds__(256)
void zero_masked_kernel(float* __restrict__ out)
{
    int row = blockIdx.x;                 // row = b*TD + t
    int b = row / TD, t = row % TD;
    if (t < g_declens[b]) return;
    int tid = threadIdx.x;
    float4 z = make_float4(0.f, 0.f, 0.f, 0.f);
    float4* dp = reinterpret_cast<float4*>(out + (long)row*VD);
    for (int i = tid; i < VD/4; i += 256) dp[i] = z;
    float* da = out + O_ALPHA + (long)row*PP;
    for (int i = tid; i < PP; i += 256) da[i] = 0.f;
}

__global__ void bias_combine_kernel(const float* __restrict__ b_ih,
                                    const float* __restrict__ b_hh)
{
    int n = blockIdx.x*blockDim.x + threadIdx.x;
    if (n < G4H) g_bias_ihh[n] = b_ih[n] + b_hh[n];
}

// all weight conversions in one kernel
struct CvtSegs {
    const float4* src[8];
    __half2*      dst[8];
    long          cum[9];
};
__global__ void cvt_all_kernel(CvtSegs segs)
{
    long i = (long)blockIdx.x*blockDim.x + threadIdx.x;
    if (i >= segs.cum[8]) return;
    int s = 0;
    #pragma unroll
    for (int k = 1; k < 8; k++) s += (i >= segs.cum[k]);
    long j = i - segs.cum[s];
    float4 v = segs.src[s][j];
    segs.dst[s][j*2]   = __floats2half2_rn(v.x, v.y);
    segs.dst[s][j*2+1] = __floats2half2_rn(v.z, v.w);
}

__global__ void embt_kernel(const float* __restrict__ emb)
{
    long idx = (long)blockIdx.x*blockDim.x + threadIdx.x;
    if (idx >= (long)MB*ED) return;
    int row = (int)(idx / ED), j = (int)(idx % ED);
    int t = row / BB, b = row % BB;
    int cap = g_caps[b*TCD + t];
    g_embt_h[idx] = __float2half(emb[(long)cap*ED + j]);
}

// one pass: gather-sorted eo -> fp16 staged copy AND column mean
__global__ void mean_eohf_kernel(const float* __restrict__ enc_out)
{
    int e = blockIdx.x*blockDim.x + threadIdx.x;
    int b = blockIdx.y;
    if (e >= ENCD) return;
    long src = ((long)g_ind[b]*PP)*ENCD + e;
    long dst = ((long)b*PP)*ENCD + e;
    float acc = 0.f;
    for (int p = 0; p < PP; p++) {
        float v = enc_out[src + (long)p*ENCD];
        g_eohf[dst + (long)p*ENCD] = __float2half(v);
        acc += v;
    }
    g_mean_h[b*ENCD + e] = __float2half(acc / (float)PP);
}

// ---------------------------------------------------------------
// FP16 64x64 GEMM, cp.async 3-stage pipelined (4 warps):
//  EPI 0: fp32 write + bias
//  EPI 5: fp16 write + bias
//  EPI 6: K-split partial fp32 (zoff)
// ---------------------------------------------------------------
template<int EPI>
__global__ __launch_bounds__(128)
void fgemm64_kernel(const __half* __restrict__ A, int lda,
                    const __half* __restrict__ W, int ldw,
                    const float* __restrict__ bias,
                    void* __restrict__ Cv, int ldc,
                    int M, int N, int K)
{
    constexpr int BM=64, BN=64, BK=32, LD=BK+8, NT=128, NS=3;
    __shared__ __half As[NS][BM*LD];
    __shared__ __half Bs[NS][BN*LD];

    const int tid = threadIdx.x;
    const int m0 = blockIdx.y*BM, n0 = blockIdx.x*BN;
    const long kbase = (long)blockIdx.z * K;
    const int warp = tid >> 5, lane = tid & 31;
    const int wm = (warp % 2)*32, wn = (warp / 2)*32;
    const int g = lane >> 2, tg = lane & 3;

    const uint32_t sAbase = (uint32_t)__cvta_generic_to_shared(&As[0][0]);
    const uint32_t sBbase = (uint32_t)__cvta_generic_to_shared(&Bs[0][0]);

    float acc[2][4][4];
    #pragma unroll
    for (int i=0;i<2;i++)
        #pragma unroll
        for (int j=0;j<4;j++)
            #pragma unroll
            for (int q=0;q<4;q++) acc[i][j][q]=0.f;

    const int KT = K / BK;

    auto load_stage = [&](int st, int k0) {
        uint32_t ab = sAbase + (uint32_t)st*(BM*LD*2);
        #pragma unroll
        for (int s = tid; s < BM*(BK/8); s += NT) {
            int r = s >> 2, kk = (s & 3)*8;
            int row = m0 + r;
            const __half* srcp = A + (long)(row < M ? row : 0)*lda + kbase + k0 + kk;
            cp16(ab + (uint32_t)(r*LD + kk)*2, srcp, row < M ? 16 : 0);
        }
        uint32_t bb = sBbase + (uint32_t)st*(BN*LD*2);
        #pragma unroll
        for (int s = tid; s < BN*(BK/8); s += NT) {
            int r = s >> 2, kk = (s & 3)*8;
            int n = n0 + r;
            const __half* srcp = W + (long)(n < N ? n : 0)*ldw + kbase + k0 + kk;
            cp16(bb + (uint32_t)(r*LD + kk)*2, srcp, n < N ? 16 : 0);
        }
        asm volatile("cp.async.commit_group;" ::: "memory");
    };

    load_stage(0, 0);
    if (KT > 1) load_stage(1, BK);
    for (int kt = 0; kt < KT; kt++) {
        if (kt + 2 < KT) {
            load_stage((kt + 2) % NS, (kt + 2)*BK);
            asm volatile("cp.async.wait_group 2;" ::: "memory");
        } else if (kt + 1 < KT) {
            asm volatile("cp.async.wait_group 1;" ::: "memory");
        } else {
            asm volatile("cp.async.wait_group 0;" ::: "memory");
        }
        __syncthreads();
        const __half* Ast = As[kt % NS];
        const __half* Bst = Bs[kt % NS];
        #pragma unroll
        for (int kk = 0; kk < BK; kk += 16) {
            uint32_t af[2][4], bf[4][2];
            #pragma unroll
            for (int i=0;i<2;i++) {
                int r0 = (wm + i*16 + g)*LD + kk + 2*tg;
                int r1 = (wm + i*16 + g + 8)*LD + kk + 2*tg;
                af[i][0] = *reinterpret_cast<const uint32_t*>(&Ast[r0]);
                af[i][1] = *reinterpret_cast<const uint32_t*>(&Ast[r1]);
                af[i][2] = *reinterpret_cast<const uint32_t*>(&Ast[r0 + 8]);
                af[i][3] = *reinterpret_cast<const uint32_t*>(&Ast[r1 + 8]);
            }
            #pragma unroll
            for (int j=0;j<4;j++) {
                int rb = (wn + j*8 + g)*LD + kk + 2*tg;
                bf[j][0] = *reinterpret_cast<const uint32_t*>(&Bst[rb]);
                bf[j][1] = *reinterpret_cast<const uint32_t*>(&Bst[rb + 8]);
            }
            #pragma unroll
            for (int i=0;i<2;i++)
                #pragma unroll
                for (int j=0;j<4;j++)
                    mma_f16(acc[i][j], af[i], bf[j]);
        }
        __syncthreads();
    }

    float* Cf = (float*)Cv;
    __half* Ch = (__half*)Cv;
    const long zoff = (EPI == 6) ? (long)blockIdx.z * M * ldc : 0;
    #pragma unroll
    for (int i=0;i<2;i++) {
        #pragma unroll
        for (int ci=0;ci<2;ci++) {
            int m = m0 + wm + i*16 + g + ci*8;
            if (m >= M) continue;
            #pragma unroll
            for (int j=0;j<4;j++) {
                #pragma unroll
                for (int cj=0;cj<2;cj++) {
                    int n = n0 + wn + j*8 + 2*tg + cj;
                    if (n >= N) continue;
                    float v = acc[i][j][ci*2+cj];
                    if      (EPI == 0) Cf[(long)m*ldc + n] = v + bias[n];
                    else if (EPI == 5) Ch[(long)m*ldc + n] = __float2half(v + bias[n]);
                    else               Cf[zoff + (long)m*ldc + n] = v;
                }
            }
        }
    }
}

// ---------------------------------------------------------------
// FP16 128x128 GEMM, cp.async 2-stage (8 warps, 32x64/warp):
//  EPI 0 fp32+bias, 5 fp16+bias, 7 compacted preds (gather rows, scatter out)
// ---------------------------------------------------------------
template<int EPI>
__global__ __launch_bounds__(256)
void fgemm128_kernel(const __half* __restrict__ A, int lda,
                     const __half* __restrict__ W, int ldw,
                     const float* __restrict__ bias,
                     void* __restrict__ Cv, int ldc,
                     int M, int N, int K)
{
    constexpr int BM=128, BN=128, BK=32, LD=BK+8, NT=256;
    __shared__ __half As[2][BM*LD];
    __shared__ __half Bs[2][BN*LD];

    const int tid = threadIdx.x;
    const int m0 = blockIdx.y*BM, n0 = blockIdx.x*BN;
    int Meff = M;
    if (EPI == 7) {
        Meff = g_nvalid;
        if (m0 >= Meff) return;
    }
    const int warp = tid >> 5, lane = tid & 31;
    const int wm = (warp % 4)*32, wn = (warp / 4)*64;
    const int g = lane >> 2, tg = lane & 3;

    const uint32_t sAbase = (uint32_t)__cvta_generic_to_shared(&As[0][0]);
    const uint32_t sBbase = (uint32_t)__cvta_generic_to_shared(&Bs[0][0]);

    float acc[2][8][4];
    #pragma unroll
    for (int i=0;i<2;i++)
        #pragma unroll
        for (int j=0;j<8;j++)
            #pragma unroll
            for (int q=0;q<4;q++) acc[i][j][q]=0.f;

    const int KT = K / BK;

    auto load_stage = [&](int st, int k0) {
        uint32_t ab = sAbase + (uint32_t)st*(BM*LD*2);
        #pragma unroll
        for (int s = tid; s < BM*(BK/8); s += NT) {
            int r = s >> 2, kk = (s & 3)*8;
            int row = m0 + r;
            long srow = 0;
            if (row < Meff) srow = (EPI == 7) ? (long)g_vsrc[row] : (long)row;
            const __half* srcp = A + srow*lda + k0 + kk;
            cp16(ab + (uint32_t)(r*LD + kk)*2, srcp, row < Meff ? 16 : 0);
        }
        uint32_t bb = sBbase + (uint32_t)st*(BN*LD*2);
        #pragma unroll
        for (int s = tid; s < BN*(BK/8); s += NT) {
            int r = s >> 2, kk = (s & 3)*8;
            int n = n0 + r;
            const __half* srcp = W + (long)(n < N ? n : 0)*ldw + k0 + kk;
            cp16(bb + (uint32_t)(r*LD + kk)*2, srcp, n < N ? 16 : 0);
        }
        asm volatile("cp.async.commit_group;" ::: "memory");
    };

    load_stage(0, 0);
    for (int kt = 0; kt < KT; kt++) {
        if (kt + 1 < KT) {
            load_stage((kt + 1) & 1, (kt + 1)*BK);
            asm volatile("cp.async.wait_group 1;" ::: "memory");
        } else {
            asm volatile("cp.async.wait_group 0;" ::: "memory");
        }
        __syncthreads();
        const __half* Ast = As[kt & 1];
        const __half* Bst = Bs[kt & 1];
        #pragma unroll
        for (int kk = 0; kk < BK; kk += 16) {
            uint32_t af[2][4], bf[8][2];
            #pragma unroll
            for (int i=0;i<2;i++) {
                int r0 = (wm + i*16 + g)*LD + kk + 2*tg;
                int r1 = (wm + i*16 + g + 8)*LD + kk + 2*tg;
                af[i][0] = *reinterpret_cast<const uint32_t*>(&Ast[r0]);
                af[i][1] = *reinterpret_cast<const uint32_t*>(&Ast[r1]);
                af[i][2] = *reinterpret_cast<const uint32_t*>(&Ast[r0 + 8]);
                af[i][3] = *reinterpret_cast<const uint32_t*>(&Ast[r1 + 8]);
            }
            #pragma unroll
            for (int j=0;j<8;j++) {
                int rb = (wn + j*8 + g)*LD + kk + 2*tg;
                bf[j][0] = *reinterpret_cast<const uint32_t*>(&Bst[rb]);
                bf[j][1] = *reinterpret_cast<const uint32_t*>(&Bst[rb + 8]);
            }
            #pragma unroll
            for (int i=0;i<2;i++)
                #pragma unroll
                for (int j=0;j<8;j++)
                    mma_f16(acc[i][j], af[i], bf[j]);
        }
        __syncthreads();
    }

    float* Cf = (float*)Cv;
    __half* Ch = (__half*)Cv;
    #pragma unroll
    for (int i=0;i<2;i++) {
        #pragma unroll
        for (int ci=0;ci<2;ci++) {
            int m = m0 + wm + i*16 + g + ci*8;
            if (m >= Meff) continue;
            long orow = (EPI == 7) ? (long)g_vdst[m] : (long)m;
            #pragma unroll
            for (int j=0;j<8;j++) {
                #pragma unroll
                for (int cj=0;cj<2;cj++) {
                    int n = n0 + wn + j*8 + 2*tg + cj;
                    if (n >= N) continue;
                    float v = acc[i][j][ci*2+cj] + bias[n];
                    if      (EPI == 0) Cf[orow*ldc + n] = v;
                    else if (EPI == 7) Cf[orow*ldc + n] = v;
                    else               Ch[orow*ldc + n] = __float2half(v);
                }
            }
        }
    }
}

// ---------------------------------------------------------------
// Per-step h-GEMM fp16, cp.async 3-stage, K-split (grid.z in {0,1}):
// weights concat along N: [W_dec(1024) | W_beta(2048) | W_hh(4096)]
// writes raw partials; consumers merge + add bias.
// ---------------------------------------------------------------
__global__ __launch_bounds__(128)
void hstep_kernel()
{
    constexpr int BM=64, BN=64, BK=32, LD=BK+8, NT=128, KC=HD/2, NS=3;
    __shared__ __half As[NS][BM*LD];
    __shared__ __half Bs[NS][BN*LD];

    const int tid = threadIdx.x;
    const int n0 = blockIdx.x*BN;
    const int z = blockIdx.z;
    const long kbase = (long)z*KC;
    const int warp = tid >> 5, lane = tid & 31;
    const int wm = (warp % 2)*32, wn = (warp / 2)*32;
    const int g = lane >> 2, tg = lane & 3;

    const uint32_t sAbase = (uint32_t)__cvta_generic_to_shared(&As[0][0]);
    const uint32_t sBbase = (uint32_t)__cvta_generic_to_shared(&Bs[0][0]);

    float acc[2][4][4];
    #pragma unroll
    for (int i=0;i<2;i++)
        #pragma unroll
        for (int j=0;j<4;j++)
            #pragma unroll
            for (int q=0;q<4;q++) acc[i][j][q]=0.f;

    const int KT = KC / BK;   // 16

    auto load_stage = [&](int st, int k0) {
        uint32_t ab = sAbase + (uint32_t)st*(BM*LD*2);
        #pragma unroll
        for (int s = tid; s < BM*(BK/8); s += NT) {
            int r = s >> 2, kk = (s & 3)*8;
            cp16(ab + (uint32_t)(r*LD + kk)*2,
                 g_hhf + (long)r*HD + kbase + k0 + kk, 16);
        }
        uint32_t bb = sBbase + (uint32_t)st*(BN*LD*2);
        #pragma unroll
        for (int s = tid; s < BN*(BK/8); s += NT) {
            int r = s >> 2, kk = (s & 3)*8;
            int gn = n0 + r;
            const __half* wrow;
            if (gn < 1024)      wrow = g_Wdec_h  + (long)gn*HD;
            else if (gn < 3072) wrow = g_Wbeta_h + (long)(gn-1024)*HD;
            else                wrow = g_Whh_h   + (long)(gn-3072)*HD;
            cp16(bb + (uint32_t)(r*LD + kk)*2, wrow + kbase + k0 + kk, 16);
        }
        asm volatile("cp.async.commit_group;" ::: "memory");
    };

    load_stage(0, 0);
    load_stage(1, BK);
    for (int kt = 0; kt < KT; kt++) {
        if (kt + 2 < KT) {
            load_stage((kt + 2) % NS, (kt + 2)*BK);
            asm volatile("cp.async.wait_group 2;" ::: "memory");
        } else if (kt + 1 < KT) {
            asm volatile("cp.async.wait_group 1;" ::: "memory");
        } else {
            asm volatile("cp.async.wait_group 0;" ::: "memory");
        }
        __syncthreads();
        const __half* Ast = As[kt % NS];
        const __half* Bst = Bs[kt % NS];
        #pragma unroll
        for (int kk = 0; kk < BK; kk += 16) {
            uint32_t af[2][4], bf[4][2];
            #pragma unroll
            for (int i=0;i<2;i++) {
                int r0 = (wm + i*16 + g)*LD + kk + 2*tg;
                int r1 = (wm + i*16 + g + 8)*LD + kk + 2*tg;
                af[i][0] = *reinterpret_cast<const uint32_t*>(&Ast[r0]);
                af[i][1] = *reinterpret_cast<const uint32_t*>(&Ast[r1]);
                af[i][2] = *reinterpret_cast<const uint32_t*>(&Ast[r0 + 8]);
                af[i][3] = *reinterpret_cast<const uint32_t*>(&Ast[r1 + 8]);
            }
            #pragma unroll
            for (int j=0;j<4;j++) {
                int rb = (wn + j*8 + g)*LD + kk + 2*tg;
                bf[j][0] = *reinterpret_cast<const uint32_t*>(&Bst[rb]);
                bf[j][1] = *reinterpret_cast<const uint32_t*>(&Bst[rb + 8]);
            }
            #pragma unroll
            for (int i=0;i<2;i++)
                #pragma unroll
                for (int j=0;j<4;j++)
                    mma_f16(acc[i][j], af[i], bf[j]);
        }
        __syncthreads();
    }

    #pragma unroll
    for (int i=0;i<2;i++) {
        #pragma unroll
        for (int ci=0;ci<2;ci++) {
            int m = wm + i*16 + g + ci*8;
            #pragma unroll
            for (int j=0;j<4;j++) {
                #pragma unroll
                for (int cj=0;cj<2;cj++) {
                    int n = n0 + wn + j*8 + 2*tg + cj;
                    float v = acc[i][j][ci*2+cj];
                    if (n < 1024)
                        g_decpart[(long)z*BB*AD + m*AD + n] = v;
                    else if (n < 3072)
                        g_betapart[(long)z*BB*ENCD + m*ENCD + (n-1024)] = v;
                    else
                        g_gpart[(long)(4+z)*BB*G4H + m*G4H + (n-3072)] = v;
                }
            }
        }
    }
}

// ---------------------------------------------------------------
// Attention scores (grid (BB,14), 128 threads; 14 p's per block)
// ---------------------------------------------------------------
__global__ __launch_bounds__(128)
void att_score_kernel(const float* __restrict__ wfull,
                      const float* __restrict__ bfull,
                      const float* __restrict__ bdec, int t)
{
    const int b = blockIdx.x;
    if (t >= g_declens[b]) return;

    __shared__ float s_dec[AD];
    __shared__ float s_wf[AD];

    const int pbase = blockIdx.y*14;
    const int tid = threadIdx.x;
    const int warp = tid >> 5, lane = tid & 31;

    for (int i = tid; i < AD; i += 128) {
        s_dec[i] = g_decpart[b*AD + i] + g_decpart[BB*AD + b*AD + i] + bdec[i];
        s_wf[i]  = wfull[i];
    }
    __syncthreads();

    const float bf = bfull[0];
    for (int pp = warp; pp < 14; pp += 4) {
        int p = pbase + pp;
        const __half2* row = reinterpret_cast<const __half2*>(
            g_encatt_hf + ((long)b*PP + p)*AD);
        float acc = 0.f;
        #pragma unroll 8
        for (int a2 = lane; a2 < AD/2; a2 += 32) {
            __half2 e2 = row[a2];
            int a = a2*2;
            float v0 = __half2float(__low2half(e2))  + s_dec[a];
            float v1 = __half2float(__high2half(e2)) + s_dec[a+1];
            v0 = v0 > 0.f ? v0 : 0.f;
            v1 = v1 > 0.f ? v1 : 0.f;
            acc = fmaf(v0, s_wf[a], acc);
            acc = fmaf(v1, s_wf[a+1], acc);
        }
        #pragma unroll
        for (int o = 16; o > 0; o >>= 1) acc += __shfl_down_sync(0xffffffffu, acc, o);
        if (lane == 0) g_score[b*PP + p] = acc + bf;
    }
}

// ---------------------------------------------------------------
// Fused softmax + context + awe. grid (ENCD/512, BB), 512 threads.
// ---------------------------------------------------------------
__global__ __launch_bounds__(512)
void ctx_awe_kernel(const float* __restrict__ bbeta,
                    float* __restrict__ out_alphas, int t)
{
    const int b = blockIdx.y;
    if (t >= g_declens[b]) return;

    __shared__ float s_al[PP];
    __shared__ float s_red[16];
    __shared__ float s_ctx[2*512];
    const int tid = threadIdx.x;
    const int warp = tid >> 5, lane = tid & 31;

    float v = (tid < PP) ? g_score[b*PP + tid] : -INFINITY;
    float m = v;
    #pragma unroll
    for (int o = 16; o > 0; o >>= 1) m = fmaxf(m, __shfl_xor_sync(0xffffffffu, m, o));
    if (lane == 0) s_red[warp] = m;
    __syncthreads();
    if (warp == 0) {
        float mm = (lane < 16) ? s_red[lane] : -INFINITY;
        #pragma unroll
        for (int o = 8; o > 0; o >>= 1) mm = fmaxf(mm, __shfl_xor_sync(0xffffffffu, mm, o));
        if (lane == 0) s_red[0] = mm;
    }
    __syncthreads();
    const float bmax = s_red[0];
    float e = (tid < PP) ? expf(v - bmax) : 0.f;
    float s = e;
    #pragma unroll
    for (int o = 16; o > 0; o >>= 1) s += __shfl_xor_sync(0xffffffffu, s, o);
    __syncthreads();
    if (lane == 0) s_red[warp] = s;
    __syncthreads();
    if (warp == 0) {
        float ss = (lane < 16) ? s_red[lane] : 0.f;
        #pragma unroll
        for (int o = 8; o > 0; o >>= 1) ss += __shfl_xor_sync(0xffffffffu, ss, o);
        if (lane == 0) s_red[0] = ss;
    }
    __syncthreads();
    const float inv = 1.f / s_red[0];
    if (tid < PP) {
        float al = e * inv;
        s_al[tid] = al;
        if (blockIdx.x == 0)
            out_alphas[((long)b*TD + t)*PP + tid] = al;
    }
    __syncthreads();

    const int half = tid >> 8;
    const int et = tid & 255;
    int e2 = blockIdx.x*256 + et;
    const int p0 = half*98;
    const __half2* base = reinterpret_cast<const __half2*>(g_eohf)
                        + ((long)b*PP + p0)*(ENCD/2) + e2;
    float a0 = 0.f, a1 = 0.f;
    #pragma unroll 7
    for (int p = 0; p < 98; p++) {
        __half2 vv = base[(long)p*(ENCD/2)];
        float al = s_al[p0 + p];
        a0 = fmaf(__half2float(__low2half(vv)),  al, a0);
        a1 = fmaf(__half2float(__high2half(vv)), al, a1);
    }
    s_ctx[tid*2]   = a0;
    s_ctx[tid*2+1] = a1;
    __syncthreads();

    if (tid < 256) {
        float c0 = s_ctx[tid*2]   + s_ctx[(tid+256)*2];
        float c1 = s_ctx[tid*2+1] + s_ctx[(tid+256)*2+1];
        int ee = e2*2;
        float bp0 = g_betapart[b*ENCD + ee]     + g_betapart[BB*ENCD + b*ENCD + ee]     + bbeta[ee];
        float bp1 = g_betapart[b*ENCD + ee + 1] + g_betapart[BB*ENCD + b*ENCD + ee + 1] + bbeta[ee+1];
        float w0 = (1.f/(1.f+expf(-bp0))) * c0;
        float w1 = (1.f/(1.f+expf(-bp1))) * c1;
        *reinterpret_cast<__half2*>(g_awehf + b*ENCD + ee) = __floats2half2_rn(w0, w1);
    }
}

// LSTM cell, 2 elems/thread: gates = P[t] + 6 partials; active b only
__global__ __launch_bounds__(256)
void lstm_kernel(int t)
{
    int idx = blockIdx.x*blockDim.x + threadIdx.x;
    if (idx >= BB*HD/2) return;
    int b = idx / (HD/2);
    if (t >= g_declens[b]) return;
    int j = (idx % (HD/2))*2;
    long base = (long)b*G4H;
    long pbase = ((long)t*BB + b)*G4H;
    float2 gi = *reinterpret_cast<const float2*>(&g_P[pbase + j]);
    float2 gf = *reinterpret_cast<const float2*>(&g_P[pbase + HD + j]);
    float2 gg = *reinterpret_cast<const float2*>(&g_P[pbase + 2*HD + j]);
    float2 go = *reinterpret_cast<const float2*>(&g_P[pbase + 3*HD + j]);
    #pragma unroll
    for (int s = 0; s < 6; s++) {
        long pb = (long)s*BB*G4H + base;
        float2 a  = *reinterpret_cast<const float2*>(&g_gpart[pb + j]);
        float2 bq = *reinterpret_cast<const float2*>(&g_gpart[pb + HD + j]);
        float2 c2 = *reinterpret_cast<const float2*>(&g_gpart[pb + 2*HD + j]);
        float2 d2 = *reinterpret_cast<const float2*>(&g_gpart[pb + 3*HD + j]);
        gi.x += a.x;  gi.y += a.y;
        gf.x += bq.x; gf.y += bq.y;
        gg.x += c2.x; gg.y += c2.y;
        go.x += d2.x; go.y += d2.y;
    }
    float2 cold = *reinterpret_cast<const float2*>(&g_c[b*HD + j]);
    float si0 = 1.f/(1.f+expf(-gi.x)), si1 = 1.f/(1.f+expf(-gi.y));
    float sf0 = 1.f/(1.f+expf(-gf.x)), sf1 = 1.f/(1.f+expf(-gf.y));
    float so0 = 1.f/(1.f+expf(-go.x)), so1 = 1.f/(1.f+expf(-go.y));
    float cn0 = sf0*cold.x + si0*tanhf(gg.x);
    float cn1 = sf1*cold.y + si1*tanhf(gg.y);
    float hn0 = so0*tanhf(cn0);
    float hn1 = so1*tanhf(cn1);
    *reinterpret_cast<__half2*>(&g_hallhf[((long)t*BB + b)*HD + j]) = __floats2half2_rn(hn0, hn1);
    *reinterpret_cast<__half2*>(&g_hhf[b*HD + j]) = __floats2half2_rn(hn0, hn1);
    *reinterpret_cast<float2*>(&g_c[b*HD + j]) = make_float2(cn0, cn1);
}

// ---------------------------------------------------------------
extern "C" void kernel_launch(void* const* d_in, const int* in_sizes, int n_in,
                              void* d_out, int out_size)
{
    const float* enc_out  = (const float*)d_in[0];
    const int*   caps_in  = (const int*)  d_in[1];
    const int*   lengths  = (const int*)  d_in[2];
    const float* W_enc    = (const float*)d_in[3];
    const float* b_enc    = (const float*)d_in[4];
    const float* W_dec    = (const float*)d_in[5];
    const float* b_dec    = (const float*)d_in[6];
    const float* W_full   = (const float*)d_in[7];
    const float* b_full   = (const float*)d_in[8];
    const float* emb      = (const float*)d_in[9];
    const float* W_ih     = (const float*)d_in[10];
    const float* b_ih     = (const float*)d_in[11];
    const float* W_hh     = (const float*)d_in[12];
    const float* b_hh     = (const float*)d_in[13];
    const float* W_init_h = (const float*)d_in[14];
    const float* b_init_h = (const float*)d_in[15];
    const float* W_init_c = (const float*)d_in[16];
    const float* b_init_c = (const float*)d_in[17];
    const float* W_beta   = (const float*)d_in[18];
    const float* b_beta   = (const float*)d_in[19];
    const float* W_fc     = (const float*)d_in[20];
    const float* b_fc     = (const float*)d_in[21];
    float* out = (float*)d_out;

    float *p_c,*p_P,*p_bihh,*p_gpart;
    __half *p_meanh,*p_hhf,*p_awehf,*p_hallhf,*p_embth,*p_enchf,*p_eohf;
    __half *p_Wenc,*p_Wdec,*p_Wbeta,*p_Whh,*p_Wih,*p_Wfc,*p_Winh,*p_Winc;
    cudaGetSymbolAddress((void**)&p_c,       g_c);
    cudaGetSymbolAddress((void**)&p_gpart,   g_gpart);
    cudaGetSymbolAddress((void**)&p_P,       g_P);
    cudaGetSymbolAddress((void**)&p_bihh,    g_bias_ihh);
    cudaGetSymbolAddress((void**)&p_meanh,   g_mean_h);
    cudaGetSymbolAddress((void**)&p_hhf,     g_hhf);
    cudaGetSymbolAddress((void**)&p_awehf,   g_awehf);
    cudaGetSymbolAddress((void**)&p_hallhf,  g_hallhf);
    cudaGetSymbolAddress((void**)&p_embth,   g_embt_h);
    cudaGetSymbolAddress((void**)&p_enchf,   g_encatt_hf);
    cudaGetSymbolAddress((void**)&p_eohf,    g_eohf);
    cudaGetSymbolAddress((void**)&p_Wenc,    g_Wenc_h);
    cudaGetSymbolAddress((void**)&p_Wdec,    g_Wdec_h);
    cudaGetSymbolAddress((void**)&p_Wbeta,   g_Wbeta_h);
    cudaGetSymbolAddress((void**)&p_Whh,     g_Whh_h);
    cudaGetSymbolAddress((void**)&p_Wih,     g_Wih_h);
    cudaGetSymbolAddress((void**)&p_Wfc,     g_Wfc_h);
    cudaGetSymbolAddress((void**)&p_Winh,    g_Winh_h);
    cudaGetSymbolAddress((void**)&p_Winc,    g_Winc_h);

    // ---------- prologue ----------
    sort_kernel<<<1, 64>>>(lengths, caps_in, out);
    zero_masked_kernel<<<BB*TD, 256>>>(out);
    bias_combine_kernel<<<G4H/256, 256>>>(b_ih, b_hh);

    {
        CvtSegs cs;
        const float* srcs[8] = {W_enc, W_dec, W_beta, W_hh, W_ih, W_fc, W_init_h, W_init_c};
        __half* dsts[8] = {p_Wenc, p_Wdec, p_Wbeta, p_Whh, p_Wih, p_Wfc, p_Winh, p_Winc};
        long lens[8] = {(long)AD*ENCD, (long)AD*HD, (long)ENCD*HD, (long)G4H*HD,
                        (long)G4H*XD, (long)VD*HD, (long)HD*ENCD, (long)HD*ENCD};
        long cum = 0;
        for (int s = 0; s < 8; s++) {
            cs.src[s] = (const float4*)srcs[s];
            cs.dst[s] = (__half2*)dsts[s];
            cs.cum[s] = cum;
            cum += lens[s]/4;
        }
        cs.cum[8] = cum;
        cvt_all_kernel<<<(int)((cum + 255)/256), 256>>>(cs);
    }

    embt_kernel<<<(int)(((long)MB*ED + 255)/256), 256>>>(emb);
    mean_eohf_kernel<<<dim3(ENCD/256, BB), 256>>>(enc_out);

    // h0 (fp16) / c0 (fp32) : (64 x 1024), K=2048
    {
        dim3 grid(HD/64, 1, 1);
        fgemm64_kernel<5><<<grid, 128>>>(p_meanh, ENCD, p_Winh, ENCD, b_init_h, p_hhf, HD, BB, HD, ENCD);
        fgemm64_kernel<0><<<grid, 128>>>(p_meanh, ENCD, p_Winc, ENCD, b_init_c, p_c,   HD, BB, HD, ENCD);
    }

    // enc_att : (12544 x 1024), K=2048 -> fp16
    {
        dim3 grid(AD/128, (BB*PP)/128);
        fgemm128_kernel<5><<<grid, 256>>>(p_eohf, ENCD, p_Wenc, ENCD, b_enc,
                                          p_enchf, AD, BB*PP, AD, ENCD);
    }

    // P = embt @ W_ih[:, :512]^T + (b_ih+b_hh) : (1984 x 4096), K=512
    {
        dim3 grid(G4H/128, (MB + 127)/128);
        fgemm128_kernel<0><<<grid, 256>>>(p_embth, ED, p_Wih, XD, p_bihh,
                                          p_P, G4H, MB, G4H, ED);
    }

    // ---------- recurrence (5 launches/step) ----------
    for (int t = 0; t < TD; t++) {
        {
            dim3 grid((1024+2048+4096)/64, 1, 2);
            hstep_kernel<<<grid, 128>>>();
        }
        att_score_kernel<<<dim3(BB, 14), 128>>>(W_full, b_full, b_dec, t);
        ctx_awe_kernel<<<dim3(ENCD/512, BB), 512>>>(b_beta, out + O_ALPHA, t);
        {
            dim3 grid(G4H/64, 1, KSPL);
            fgemm64_kernel<6><<<grid, 128>>>(p_awehf, ENCD, p_Wih + ED, XD, nullptr,
                                             p_gpart, G4H, BB, G4H, KCH);
        }
        lstm_kernel<<<(BB*HD/2 + 255)/256, 256>>>(t);
    }

    // ---------- compacted predictions : (n_valid x 10000), K=1024 ----------
    {
        dim3 grid((VD + 127)/128, (MB + 127)/128);
        fgemm128_kernel<7><<<grid, 256>>>(p_hallhf, HD, p_Wfc, HD, b_fc,
                                          out + O_PRED, VD, MB, VD, HD);
    }
}